// round 11
// baseline (speedup 1.0000x reference)
#include <cuda_runtime.h>
#include <cuda_bf16.h>
#include <cuda_fp16.h>
#include <cstdint>

#define B_ 4
#define S_ 2048
#define D_ 512
#define H_ 8
#define DK_ 64
#define F_ 2048
#define K_ 9
#define PAD_ 4
#define EPSLN 1e-5f

static const int MROWS = B_ * S_;  // 8192

// ---------------- scratch ----------------
__device__ float g_tmp[B_ * S_ * D_];
__device__ float g_x[B_ * S_ * D_];
__device__ float g_ffn[2 * B_ * S_ * D_];
__device__ __nv_bfloat16 g_srcb[B_ * S_ * D_];
__device__ __nv_bfloat16 g_wqb[D_ * D_];
__device__ __nv_bfloat16 g_wkb[D_ * D_];
__device__ __nv_bfloat16 g_wvb[D_ * D_];
__device__ __nv_bfloat16 g_wob[D_ * D_];
__device__ __nv_bfloat16 g_qb[B_ * S_ * D_];
__device__ __nv_bfloat16 g_kb[B_ * S_ * D_];
__device__ __nv_bfloat16 g_vb[B_ * S_ * D_];
__device__ __nv_bfloat16 g_ctxb[B_ * S_ * D_];
__device__ __half g_xf[B_ * S_ * D_];
__device__ __half g_h1f[B_ * S_ * F_];
__device__ __half g_w1f[F_ * K_ * D_];
__device__ __half g_w2f[D_ * K_ * F_];

// ================= helpers =================
__device__ __forceinline__ uint32_t smem_u32(const void* p) {
    uint32_t a;
    asm("{ .reg .u64 t; cvta.to.shared.u64 t, %1; cvt.u32.u64 %0, t; }" : "=r"(a) : "l"(p));
    return a;
}
__device__ __forceinline__ void cp16(uint32_t dst, const void* src, uint32_t sz) {
    asm volatile("cp.async.cg.shared.global [%0], [%1], 16, %2;"
                 :: "r"(dst), "l"(src), "r"(sz) : "memory");
}
__device__ __forceinline__ void mma_bf16(float* d, const uint32_t* a, const uint32_t* b) {
    asm volatile(
        "mma.sync.aligned.m16n8k16.row.col.f32.bf16.bf16.f32 "
        "{%0,%1,%2,%3}, {%4,%5,%6,%7}, {%8,%9}, {%0,%1,%2,%3};"
        : "+f"(d[0]), "+f"(d[1]), "+f"(d[2]), "+f"(d[3])
        : "r"(a[0]), "r"(a[1]), "r"(a[2]), "r"(a[3]), "r"(b[0]), "r"(b[1]));
}
__device__ __forceinline__ void mma_f16(float* d, const uint32_t* a, const uint32_t* b) {
    asm volatile(
        "mma.sync.aligned.m16n8k16.row.col.f32.f16.f16.f32 "
        "{%0,%1,%2,%3}, {%4,%5,%6,%7}, {%8,%9}, {%0,%1,%2,%3};"
        : "+f"(d[0]), "+f"(d[1]), "+f"(d[2]), "+f"(d[3])
        : "r"(a[0]), "r"(a[1]), "r"(a[2]), "r"(a[3]), "r"(b[0]), "r"(b[1]));
}
__device__ __forceinline__ uint32_t packbf(float x, float y) {
    uint32_t r;
    asm("cvt.rn.bf16x2.f32 %0, %1, %2;" : "=r"(r) : "f"(y), "f"(x));
    return r;
}

// ============== conv, M-tile 256, tap reuse (A tile 264 rows, all 9 taps) ====
template <int CIN, int NF, int NDBLK, bool RELU>
__global__ void __launch_bounds__(256, 1)
conv_tap(const __half* __restrict__ Af, const __half* __restrict__ Bf,
         const float* __restrict__ bias,
         __half* __restrict__ ofh, float* __restrict__ off) {
    constexpr int KTOT = K_ * CIN;
    constexpr int RSTR = 144;
    constexpr int ATILE = 264 * RSTR;   // 38016
    constexpr int BTILE = 128 * RSTR;   // 18432
    constexpr int NIT = NDBLK * 9;

    extern __shared__ __align__(16) char sm[];
    const int tid = threadIdx.x;
    const int lane = tid & 31;
    const int w = tid >> 5;
    const int wm = w & 3;     // 4 m-quadrants of 64 rows
    const int wn = w >> 2;    // 2 n-halves of 64 cols
    const int m0 = blockIdx.y * 256;
    const int n0 = blockIdx.x * 128;
    const int dz0 = blockIdx.z * NDBLK;
    const int bbase = m0 & ~(S_ - 1);
    const int s0 = m0 & (S_ - 1);

    float acc[4][8][4];
#pragma unroll
    for (int i = 0; i < 4; i++)
#pragma unroll
        for (int j = 0; j < 8; j++)
#pragma unroll
            for (int e = 0; e < 4; e++) acc[i][j][e] = 0.f;

    const uint32_t smu = smem_u32(sm);
    const uint32_t A0u = smu, A1u = smu + ATILE;
    const uint32_t B0u = smu + 2 * ATILE, B1u = smu + 2 * ATILE + BTILE;

    auto loadA = [&](int dblk, int buf) {
        uint32_t base = buf ? A1u : A0u;
        int dcol = (dz0 + dblk) << 6;
        for (int t = tid; t < 2112; t += 256) {   // 264 rows x 8 chunks
            int r = t >> 3, u = t & 7;
            int srow = s0 + r - PAD_;
            bool val = (unsigned)srow < (unsigned)S_;
            long aoff = (long)(bbase + (val ? srow : 0)) * CIN + dcol + (u << 3);
            cp16(base + r * RSTR + (u << 4), Af + aoff, val ? 16u : 0u);
        }
    };
    auto loadB = [&](int dblk, int k, int buf) {
        uint32_t base = buf ? B1u : B0u;
        long kk0 = (long)k * CIN + ((dz0 + dblk) << 6);
#pragma unroll
        for (int j = 0; j < 4; j++) {
            int idx = tid + j * 256;
            int r = idx >> 3, u = idx & 7;
            cp16(base + r * RSTR + (u << 4), Bf + (long)(n0 + r) * KTOT + kk0 + (u << 3), 16);
        }
    };

    loadA(0, 0);
    loadB(0, 0, 0);
    asm volatile("cp.async.commit_group;" ::: "memory");

    const int arow = lane >> 2;
    const int acol = (lane & 3) * 4;
    int abuf = 0;

    for (int i = 0; i < NIT; i++) {
        const int dblk = i / 9;
        const int k = i - dblk * 9;
        if (i + 1 < NIT) {
            const int k1 = (k == 8) ? 0 : k + 1;
            const int d1 = (k == 8) ? dblk + 1 : dblk;
            loadB(d1, k1, (i + 1) & 1);
            if (k == 8) loadA(d1, abuf ^ 1);
        }
        asm volatile("cp.async.commit_group;" ::: "memory");
        asm volatile("cp.async.wait_group 1;" ::: "memory");
        __syncthreads();

        const char* A_s = sm + (abuf ? ATILE : 0);
        const char* B_s = sm + 2 * ATILE + ((i & 1) ? BTILE : 0);

#pragma unroll
        for (int ks = 0; ks < 4; ks++) {
            const int kb = ks * 32;
            uint32_t ar[4][4], br[8][2];
#pragma unroll
            for (int mi = 0; mi < 4; mi++) {
                const char* ba = A_s + (wm * 64 + mi * 16 + arow + k) * RSTR + kb + acol;
                ar[mi][0] = *(const uint32_t*)ba;
                ar[mi][1] = *(const uint32_t*)(ba + 8 * RSTR);
                ar[mi][2] = *(const uint32_t*)(ba + 16);
                ar[mi][3] = *(const uint32_t*)(ba + 8 * RSTR + 16);
            }
#pragma unroll
            for (int nj = 0; nj < 8; nj++) {
                const char* bb = B_s + (wn * 64 + nj * 8 + arow) * RSTR + kb + acol;
                br[nj][0] = *(const uint32_t*)bb;
                br[nj][1] = *(const uint32_t*)(bb + 16);
            }
#pragma unroll
            for (int mi = 0; mi < 4; mi++)
#pragma unroll
                for (int nj = 0; nj < 8; nj++) mma_f16(acc[mi][nj], ar[mi], br[nj]);
        }
        __syncthreads();
        if (k == 8) abuf ^= 1;
    }

    const int mbase = m0 + wm * 64;
    const int nb0 = n0 + wn * 64;
    const long zoff = (long)blockIdx.z * MROWS * D_;
#pragma unroll
    for (int mi = 0; mi < 4; mi++) {
        const int m = mbase + mi * 16 + arow;
#pragma unroll
        for (int nj = 0; nj < 8; nj++) {
            const int n = nb0 + nj * 8 + (lane & 3) * 2;
            if (RELU) {
                const float bv0 = bias[n], bv1 = bias[n + 1];
                __half2 p0, p1;
                p0.x = __float2half_rn(fmaxf(acc[mi][nj][0] + bv0, 0.f));
                p0.y = __float2half_rn(fmaxf(acc[mi][nj][1] + bv1, 0.f));
                p1.x = __float2half_rn(fmaxf(acc[mi][nj][2] + bv0, 0.f));
                p1.y = __float2half_rn(fmaxf(acc[mi][nj][3] + bv1, 0.f));
                *(__half2*)(ofh + (long)m * NF + n) = p0;
                *(__half2*)(ofh + (long)(m + 8) * NF + n) = p1;
            } else {
                const float bv0 = blockIdx.z == 0 ? bias[n] : 0.f;
                const float bv1 = blockIdx.z == 0 ? bias[n + 1] : 0.f;
                *(float2*)(off + zoff + (long)m * NF + n) =
                    make_float2(acc[mi][nj][0] + bv0, acc[mi][nj][1] + bv1);
                *(float2*)(off + zoff + (long)(m + 8) * NF + n) =
                    make_float2(acc[mi][nj][2] + bv0, acc[mi][nj][3] + bv1);
            }
        }
    }
}

// ============== bf16 linear (QKV projections), z selects weight ==============
__global__ void __launch_bounds__(256, 2)
lin_qkv(const __nv_bfloat16* __restrict__ A,
        const __nv_bfloat16* __restrict__ W0, const __nv_bfloat16* __restrict__ W1,
        const __nv_bfloat16* __restrict__ W2,
        const float* __restrict__ bi0, const float* __restrict__ bi1,
        const float* __restrict__ bi2,
        __nv_bfloat16* __restrict__ o0, __nv_bfloat16* __restrict__ o1,
        __nv_bfloat16* __restrict__ o2) {
    constexpr int RSTR = 144;
    constexpr int TILE = 128 * RSTR;
    constexpr int BUF = 2 * TILE;

    extern __shared__ __align__(16) char sm[];
    const int z = blockIdx.z;
    const __nv_bfloat16* W = (z == 0) ? W0 : (z == 1) ? W1 : W2;
    const float* bias = (z == 0) ? bi0 : (z == 1) ? bi1 : bi2;
    __nv_bfloat16* out = (z == 0) ? o0 : (z == 1) ? o1 : o2;

    const int tid = threadIdx.x;
    const int lane = tid & 31;
    const int w = tid >> 5;
    const int wm = w & 3;
    const int wn = w >> 2;
    const int m0 = blockIdx.y * 128;
    const int n0 = blockIdx.x * 128;

    float acc[2][8][4];
#pragma unroll
    for (int i = 0; i < 2; i++)
#pragma unroll
        for (int j = 0; j < 8; j++)
#pragma unroll
            for (int e = 0; e < 4; e++) acc[i][j][e] = 0.f;

    const uint32_t smu = smem_u32(sm);
    auto prefetch = [&](int c) {
        uint32_t bpu = smu + (c & 1) * BUF;
#pragma unroll
        for (int j = 0; j < 4; j++) {
            int idx = tid + j * 256;
            int r = idx >> 3, u = idx & 7;
            uint32_t d = bpu + r * RSTR + (u << 4);
            cp16(d, A + (long)(m0 + r) * D_ + c * 64 + (u << 3), 16);
            cp16(d + TILE, W + (long)(n0 + r) * D_ + c * 64 + (u << 3), 16);
        }
    };

    prefetch(0);
    asm volatile("cp.async.commit_group;" ::: "memory");
    const int arow = lane >> 2;
    const int acol = (lane & 3) * 4;

    for (int c = 0; c < D_ / 64; ++c) {
        if (c + 1 < D_ / 64) {
            prefetch(c + 1);
            asm volatile("cp.async.commit_group;" ::: "memory");
            asm volatile("cp.async.wait_group 1;" ::: "memory");
        } else {
            asm volatile("cp.async.wait_group 0;" ::: "memory");
        }
        __syncthreads();
        const char* bp = sm + (c & 1) * BUF;
#pragma unroll
        for (int ks = 0; ks < 4; ks++) {
            const int kb = ks * 32;
            uint32_t ar[2][4], br[8][2];
#pragma unroll
            for (int mi = 0; mi < 2; mi++) {
                const char* ba = bp + (wm * 32 + mi * 16 + arow) * RSTR + kb + acol;
                ar[mi][0] = *(const uint32_t*)ba;
                ar[mi][1] = *(const uint32_t*)(ba + 8 * RSTR);
                ar[mi][2] = *(const uint32_t*)(ba + 16);
                ar[mi][3] = *(const uint32_t*)(ba + 8 * RSTR + 16);
            }
#pragma unroll
            for (int nj = 0; nj < 8; nj++) {
                const char* bb = bp + TILE + (wn * 64 + nj * 8 + arow) * RSTR + kb + acol;
                br[nj][0] = *(const uint32_t*)bb;
                br[nj][1] = *(const uint32_t*)(bb + 16);
            }
#pragma unroll
            for (int mi = 0; mi < 2; mi++)
#pragma unroll
                for (int nj = 0; nj < 8; nj++) mma_bf16(acc[mi][nj], ar[mi], br[nj]);
        }
        __syncthreads();
    }

    const int mbase = m0 + wm * 32;
    const int nb0 = n0 + wn * 64;
#pragma unroll
    for (int mi = 0; mi < 2; mi++) {
        const int m = mbase + mi * 16 + arow;
#pragma unroll
        for (int nj = 0; nj < 8; nj++) {
            const int n = nb0 + nj * 8 + (lane & 3) * 2;
            const float bv0 = bias[n], bv1 = bias[n + 1];
            __nv_bfloat162 p0, p1;
            p0.x = __float2bfloat16_rn(acc[mi][nj][0] + bv0);
            p0.y = __float2bfloat16_rn(acc[mi][nj][1] + bv1);
            p1.x = __float2bfloat16_rn(acc[mi][nj][2] + bv0);
            p1.y = __float2bfloat16_rn(acc[mi][nj][3] + bv1);
            *(__nv_bfloat162*)(out + (long)m * D_ + n) = p0;
            *(__nv_bfloat162*)(out + (long)(m + 8) * D_ + n) = p1;
        }
    }
}

// ============== bf16 linear, fp32 output (wo projection) =====================
__global__ void __launch_bounds__(256, 2)
lin_o(const __nv_bfloat16* __restrict__ A, const __nv_bfloat16* __restrict__ W,
      const float* __restrict__ bias, float* __restrict__ out) {
    constexpr int RSTR = 144;
    constexpr int TILE = 128 * RSTR;
    constexpr int BUF = 2 * TILE;

    extern __shared__ __align__(16) char sm[];
    const int tid = threadIdx.x;
    const int lane = tid & 31;
    const int w = tid >> 5;
    const int wm = w & 3;
    const int wn = w >> 2;
    const int m0 = blockIdx.y * 128;
    const int n0 = blockIdx.x * 128;

    float acc[2][8][4];
#pragma unroll
    for (int i = 0; i < 2; i++)
#pragma unroll
        for (int j = 0; j < 8; j++)
#pragma unroll
            for (int e = 0; e < 4; e++) acc[i][j][e] = 0.f;

    const uint32_t smu = smem_u32(sm);
    auto prefetch = [&](int c) {
        uint32_t bpu = smu + (c & 1) * BUF;
#pragma unroll
        for (int j = 0; j < 4; j++) {
            int idx = tid + j * 256;
            int r = idx >> 3, u = idx & 7;
            uint32_t d = bpu + r * RSTR + (u << 4);
            cp16(d, A + (long)(m0 + r) * D_ + c * 64 + (u << 3), 16);
            cp16(d + TILE, W + (long)(n0 + r) * D_ + c * 64 + (u << 3), 16);
        }
    };

    prefetch(0);
    asm volatile("cp.async.commit_group;" ::: "memory");
    const int arow = lane >> 2;
    const int acol = (lane & 3) * 4;

    for (int c = 0; c < D_ / 64; ++c) {
        if (c + 1 < D_ / 64) {
            prefetch(c + 1);
            asm volatile("cp.async.commit_group;" ::: "memory");
            asm volatile("cp.async.wait_group 1;" ::: "memory");
        } else {
            asm volatile("cp.async.wait_group 0;" ::: "memory");
        }
        __syncthreads();
        const char* bp = sm + (c & 1) * BUF;
#pragma unroll
        for (int ks = 0; ks < 4; ks++) {
            const int kb = ks * 32;
            uint32_t ar[2][4], br[8][2];
#pragma unroll
            for (int mi = 0; mi < 2; mi++) {
                const char* ba = bp + (wm * 32 + mi * 16 + arow) * RSTR + kb + acol;
                ar[mi][0] = *(const uint32_t*)ba;
                ar[mi][1] = *(const uint32_t*)(ba + 8 * RSTR);
                ar[mi][2] = *(const uint32_t*)(ba + 16);
                ar[mi][3] = *(const uint32_t*)(ba + 8 * RSTR + 16);
            }
#pragma unroll
            for (int nj = 0; nj < 8; nj++) {
                const char* bb = bp + TILE + (wn * 64 + nj * 8 + arow) * RSTR + kb + acol;
                br[nj][0] = *(const uint32_t*)bb;
                br[nj][1] = *(const uint32_t*)(bb + 16);
            }
#pragma unroll
            for (int mi = 0; mi < 2; mi++)
#pragma unroll
                for (int nj = 0; nj < 8; nj++) mma_bf16(acc[mi][nj], ar[mi], br[nj]);
        }
        __syncthreads();
    }

    const int mbase = m0 + wm * 32;
    const int nb0 = n0 + wn * 64;
#pragma unroll
    for (int mi = 0; mi < 2; mi++) {
        const int m = mbase + mi * 16 + arow;
#pragma unroll
        for (int nj = 0; nj < 8; nj++) {
            const int n = nb0 + nj * 8 + (lane & 3) * 2;
            const float bv0 = bias[n], bv1 = bias[n + 1];
            *(float2*)(out + (long)m * D_ + n) =
                make_float2(acc[mi][nj][0] + bv0, acc[mi][nj][1] + bv1);
            *(float2*)(out + (long)(m + 8) * D_ + n) =
                make_float2(acc[mi][nj][2] + bv0, acc[mi][nj][3] + bv1);
        }
    }
}

// ============== fused flash attention: 128-row Q tile, 8 warps ===============
__global__ void __launch_bounds__(256, 2)
flash_k(const __nv_bfloat16* __restrict__ qg, const __nv_bfloat16* __restrict__ kg,
        const __nv_bfloat16* __restrict__ vg, __nv_bfloat16* __restrict__ ctx) {
    constexpr int QPITCH = 144;
    constexpr int KPITCH = 144;
    constexpr int VPITCH = 276;
    extern __shared__ __align__(16) char sm[];
    char* Qs = sm;
    char* Ks = sm + 128 * QPITCH;
    char* Vt = Ks + 128 * KPITCH;

    const int tid = threadIdx.x;
    const int lane = tid & 31;
    const int w = tid >> 5;
    const int bh = blockIdx.y;
    const int b = bh >> 3, h = bh & 7;
    const int q0 = blockIdx.x * 128;
    const long hoff = (long)b * S_ * D_ + h * DK_;
    const __nv_bfloat16* qp = qg + hoff;
    const __nv_bfloat16* kp = kg + hoff;
    const __nv_bfloat16* vp = vg + hoff;

    const uint32_t qsu = smem_u32(Qs);
    const uint32_t ksu = smem_u32(Ks);

#pragma unroll
    for (int i = 0; i < 4; i++) {
        int idx = tid + i * 256;
        int r = idx >> 3, u = idx & 7;
        cp16(qsu + r * QPITCH + (u << 4), qp + (long)(q0 + r) * D_ + (u << 3), 16);
    }
    asm volatile("cp.async.commit_group;" ::: "memory");
    asm volatile("cp.async.wait_group 0;" ::: "memory");
    __syncthreads();

    const int arow = lane >> 2;
    const int acol = (lane & 3) * 4;
    uint32_t qf[4][4];
#pragma unroll
    for (int ks = 0; ks < 4; ks++) {
        const char* ba = Qs + (w * 16 + arow) * QPITCH + ks * 32 + acol;
        qf[ks][0] = *(const uint32_t*)ba;
        qf[ks][1] = *(const uint32_t*)(ba + 8 * QPITCH);
        qf[ks][2] = *(const uint32_t*)(ba + 16);
        qf[ks][3] = *(const uint32_t*)(ba + 8 * QPITCH + 16);
    }

    float oacc[8][4];
#pragma unroll
    for (int j = 0; j < 8; j++)
#pragma unroll
        for (int e = 0; e < 4; e++) oacc[j][e] = 0.f;
    float lsum0 = 0.f, lsum1 = 0.f;

    for (int t = 0; t < S_ / 128; ++t) {
        __syncthreads();
#pragma unroll
        for (int i = 0; i < 4; i++) {
            int idx = tid + i * 256;
            int r = idx >> 3, u = idx & 7;
            cp16(ksu + r * KPITCH + (u << 4), kp + (long)(t * 128 + r) * D_ + (u << 3), 16);
        }
        asm volatile("cp.async.commit_group;" ::: "memory");
#pragma unroll
        for (int i = 0; i < 2; i++) {
            int idx = tid + i * 256;
            int k2 = idx >> 3, u = idx & 7;
            const uint4 a = *(const uint4*)(vp + (long)(t * 128 + 2 * k2) * D_ + (u << 3));
            const uint4 bq = *(const uint4*)(vp + (long)(t * 128 + 2 * k2 + 1) * D_ + (u << 3));
            const uint32_t va[4] = {a.x, a.y, a.z, a.w};
            const uint32_t vb[4] = {bq.x, bq.y, bq.z, bq.w};
#pragma unroll
            for (int e = 0; e < 8; e++) {
                uint32_t lo = (va[e >> 1] >> ((e & 1) * 16)) & 0xffffu;
                uint32_t hi = (vb[e >> 1] >> ((e & 1) * 16)) & 0xffffu;
                *(uint32_t*)(Vt + (u * 8 + e) * VPITCH + k2 * 4) = lo | (hi << 16);
            }
        }
        asm volatile("cp.async.wait_group 0;" ::: "memory");
        __syncthreads();

        float sacc[16][4];
#pragma unroll
        for (int j = 0; j < 16; j++)
#pragma unroll
            for (int e = 0; e < 4; e++) sacc[j][e] = 0.f;
#pragma unroll
        for (int ks = 0; ks < 4; ks++) {
#pragma unroll
            for (int nt = 0; nt < 16; nt++) {
                const char* bb = Ks + (nt * 8 + arow) * KPITCH + ks * 32 + acol;
                uint32_t br[2];
                br[0] = *(const uint32_t*)bb;
                br[1] = *(const uint32_t*)(bb + 16);
                mma_bf16(sacc[nt], qf[ks], br);
            }
        }
#pragma unroll
        for (int nt = 0; nt < 16; nt++) {
            float p0 = __expf(sacc[nt][0] * 0.125f);
            float p1 = __expf(sacc[nt][1] * 0.125f);
            float p2 = __expf(sacc[nt][2] * 0.125f);
            float p3 = __expf(sacc[nt][3] * 0.125f);
            sacc[nt][0] = p0; sacc[nt][1] = p1; sacc[nt][2] = p2; sacc[nt][3] = p3;
            lsum0 += p0 + p1;
            lsum1 += p2 + p3;
        }
#pragma unroll
        for (int kt = 0; kt < 8; kt++) {
            uint32_t pa[4];
            pa[0] = packbf(sacc[2 * kt][0], sacc[2 * kt][1]);
            pa[1] = packbf(sacc[2 * kt][2], sacc[2 * kt][3]);
            pa[2] = packbf(sacc[2 * kt + 1][0], sacc[2 * kt + 1][1]);
            pa[3] = packbf(sacc[2 * kt + 1][2], sacc[2 * kt + 1][3]);
#pragma unroll
            for (int nt = 0; nt < 8; nt++) {
                const char* bb = Vt + (nt * 8 + arow) * VPITCH + kt * 32 + acol;
                uint32_t br[2];
                br[0] = *(const uint32_t*)bb;
                br[1] = *(const uint32_t*)(bb + 16);
                mma_bf16(oacc[nt], pa, br);
            }
        }
    }

    lsum0 += __shfl_xor_sync(0xffffffffu, lsum0, 1);
    lsum0 += __shfl_xor_sync(0xffffffffu, lsum0, 2);
    lsum1 += __shfl_xor_sync(0xffffffffu, lsum1, 1);
    lsum1 += __shfl_xor_sync(0xffffffffu, lsum1, 2);
    const float inv0 = 1.f / lsum0;
    const float inv1 = 1.f / lsum1;

    const int row0 = q0 + w * 16 + arow;
#pragma unroll
    for (int nt = 0; nt < 8; nt++) {
        const int col = h * DK_ + nt * 8 + (lane & 3) * 2;
        *(uint32_t*)(ctx + ((long)b * S_ + row0) * D_ + col) =
            packbf(oacc[nt][0] * inv0, oacc[nt][1] * inv0);
        *(uint32_t*)(ctx + ((long)b * S_ + row0 + 8) * D_ + col) =
            packbf(oacc[nt][2] * inv1, oacc[nt][3] * inv1);
    }
}

// ---------------- converts & weight reorders (coalesced) ---------------------
__global__ void f2bf(const float* __restrict__ in, __nv_bfloat16* __restrict__ out, int n) {
    int i = (blockIdx.x * 256 + threadIdx.x) * 4;
    if (i >= n) return;
    float4 v = *(const float4*)(in + i);
    __nv_bfloat16 o[4] = {__float2bfloat16_rn(v.x), __float2bfloat16_rn(v.y),
                          __float2bfloat16_rn(v.z), __float2bfloat16_rn(v.w)};
    *(uint2*)(out + i) = *(uint2*)o;
}
__global__ void f2bf_w4(const float* __restrict__ w0, const float* __restrict__ w1,
                        const float* __restrict__ w2, const float* __restrict__ w3,
                        __nv_bfloat16* __restrict__ o0, __nv_bfloat16* __restrict__ o1,
                        __nv_bfloat16* __restrict__ o2, __nv_bfloat16* __restrict__ o3) {
    const int z = blockIdx.y;
    const float* in = (z == 0) ? w0 : (z == 1) ? w1 : (z == 2) ? w2 : w3;
    __nv_bfloat16* out = (z == 0) ? o0 : (z == 1) ? o1 : (z == 2) ? o2 : o3;
    int i = (blockIdx.x * 256 + threadIdx.x) * 4;
    if (i >= D_ * D_) return;
    float4 v = *(const float4*)(in + i);
    __nv_bfloat16 o[4] = {__float2bfloat16_rn(v.x), __float2bfloat16_rn(v.y),
                          __float2bfloat16_rn(v.z), __float2bfloat16_rn(v.w)};
    *(uint2*)(out + i) = *(uint2*)o;
}
__global__ void cvt_w1_t(const float* __restrict__ w, __half* __restrict__ o) {
    __shared__ float s[D_ * K_];
    const int f = blockIdx.x;
    const float* src = w + (long)f * (D_ * K_);
    for (int j = threadIdx.x; j < D_ * K_; j += 256) s[j] = src[j];
    __syncthreads();
    __half* dst = o + (long)f * (K_ * D_);
    for (int t = threadIdx.x; t < K_ * D_; t += 256) {
        int k = t / D_, d = t - k * D_;
        dst[t] = __float2half_rn(s[d * K_ + k]);
    }
}
__global__ void cvt_w2_t(const float* __restrict__ w, __half* __restrict__ o) {
    __shared__ __half s[F_ * K_];
    const int d = blockIdx.x;
    const float* src = w + (long)d * (F_ * K_);
    for (int j = threadIdx.x; j < F_ * K_; j += 256) s[j] = __float2half_rn(src[j]);
    __syncthreads();
    __half* dst = o + (long)d * (K_ * F_);
    for (int t = threadIdx.x; t < K_ * F_; t += 256) {
        int k = t / F_, fi = t - k * F_;
        dst[t] = s[fi * K_ + k];
    }
}

// ------------- residual add + LayerNorm (1 or 2 residual-add inputs) --------
template <int NB, bool EMIT16>
__global__ void add_ln_k(const float* __restrict__ a, const float* __restrict__ b0,
                         const float* __restrict__ b1,
                         const float* __restrict__ g, const float* __restrict__ be,
                         float* __restrict__ o, __half* __restrict__ o16) {
    __shared__ float sh[8];
    long row = blockIdx.x;
    int t = threadIdx.x;
    int lane = t & 31, wid = t >> 5;
    float4 va = ((const float4*)(a + row * D_))[t];
    float4 vb = ((const float4*)(b0 + row * D_))[t];
    float4 v;
    v.x = va.x + vb.x; v.y = va.y + vb.y; v.z = va.z + vb.z; v.w = va.w + vb.w;
    if (NB == 2) {
        float4 vc = ((const float4*)(b1 + row * D_))[t];
        v.x += vc.x; v.y += vc.y; v.z += vc.z; v.w += vc.w;
    }
    float s = v.x + v.y + v.z + v.w;
    float s2 = v.x * v.x + v.y * v.y + v.z * v.z + v.w * v.w;
#pragma unroll
    for (int off = 16; off; off >>= 1) {
        s += __shfl_xor_sync(0xffffffffu, s, off);
        s2 += __shfl_xor_sync(0xffffffffu, s2, off);
    }
    if (lane == 0) { sh[wid] = s; sh[4 + wid] = s2; }
    __syncthreads();
    float S = sh[0] + sh[1] + sh[2] + sh[3];
    float S2 = sh[4] + sh[5] + sh[6] + sh[7];
    float mean = S * (1.f / D_);
    float var = S2 * (1.f / D_) - mean * mean;
    float inv = rsqrtf(var + EPSLN);
    float4 g4 = ((const float4*)g)[t];
    float4 b4 = ((const float4*)be)[t];
    float4 r;
    r.x = (v.x - mean) * inv * g4.x + b4.x;
    r.y = (v.y - mean) * inv * g4.y + b4.y;
    r.z = (v.z - mean) * inv * g4.z + b4.z;
    r.w = (v.w - mean) * inv * g4.w + b4.w;
    ((float4*)(o + row * D_))[t] = r;
    if (EMIT16) {
        __half hs[4] = {__float2half_rn(r.x), __float2half_rn(r.y),
                        __float2half_rn(r.z), __float2half_rn(r.w)};
        *(uint2*)(o16 + row * D_ + t * 4) = *(uint2*)hs;
    }
}

// ---------------- launch ------------------------------------------------------
extern "C" void kernel_launch(void* const* d_in, const int* in_sizes, int n_in,
                              void* d_out, int out_size) {
    const float* src = (const float*)d_in[0];
    const float* wq = (const float*)d_in[2];
    const float* bq = (const float*)d_in[3];
    const float* wk = (const float*)d_in[4];
    const float* bk = (const float*)d_in[5];
    const float* wv = (const float*)d_in[6];
    const float* bv = (const float*)d_in[7];
    const float* wo = (const float*)d_in[8];
    const float* bo = (const float*)d_in[9];
    const float* c1w = (const float*)d_in[10];
    const float* c1b = (const float*)d_in[11];
    const float* c2w = (const float*)d_in[12];
    const float* c2b = (const float*)d_in[13];
    const float* g1 = (const float*)d_in[14];
    const float* b1 = (const float*)d_in[15];
    const float* g2 = (const float*)d_in[16];
    const float* b2 = (const float*)d_in[17];
    float* out = (float*)d_out;

    float *tmp, *x, *ffn;
    __nv_bfloat16 *srcb, *wqb, *wkb, *wvb, *wob, *qb, *kb, *vb, *ctxb;
    __half *xf, *h1f, *w1f, *w2f;
    cudaGetSymbolAddress((void**)&tmp, g_tmp);
    cudaGetSymbolAddress((void**)&x, g_x);
    cudaGetSymbolAddress((void**)&ffn, g_ffn);
    cudaGetSymbolAddress((void**)&srcb, g_srcb);
    cudaGetSymbolAddress((void**)&wqb, g_wqb);
    cudaGetSymbolAddress((void**)&wkb, g_wkb);
    cudaGetSymbolAddress((void**)&wvb, g_wvb);
    cudaGetSymbolAddress((void**)&wob, g_wob);
    cudaGetSymbolAddress((void**)&qb, g_qb);
    cudaGetSymbolAddress((void**)&kb, g_kb);
    cudaGetSymbolAddress((void**)&vb, g_vb);
    cudaGetSymbolAddress((void**)&ctxb, g_ctxb);
    cudaGetSymbolAddress((void**)&xf, g_xf);
    cudaGetSymbolAddress((void**)&h1f, g_h1f);
    cudaGetSymbolAddress((void**)&w1f, g_w1f);
    cudaGetSymbolAddress((void**)&w2f, g_w2f);

    const int CSMEM = 2 * 264 * 144 + 2 * 128 * 144;   // 112896
    const int LSMEM = 2 * 2 * 128 * 144;                // 73728
    const int FSMEM = 128 * 144 + 128 * 144 + 64 * 276; // 54528
    cudaFuncSetAttribute(conv_tap<D_, F_, D_ / 64, true>,
                         cudaFuncAttributeMaxDynamicSharedMemorySize, CSMEM);
    cudaFuncSetAttribute(conv_tap<F_, D_, F_ / 128, false>,
                         cudaFuncAttributeMaxDynamicSharedMemorySize, CSMEM);
    cudaFuncSetAttribute(lin_qkv, cudaFuncAttributeMaxDynamicSharedMemorySize, LSMEM);
    cudaFuncSetAttribute(lin_o, cudaFuncAttributeMaxDynamicSharedMemorySize, LSMEM);
    cudaFuncSetAttribute(flash_k, cudaFuncAttributeMaxDynamicSharedMemorySize, FSMEM);

    cvt_w1_t<<<F_, 256>>>(c1w, w1f);
    cvt_w2_t<<<D_, 256>>>(c2w, w2f);
    f2bf<<<(MROWS * D_ / 4 + 255) / 256, 256>>>(src, srcb, MROWS * D_);
    f2bf_w4<<<dim3((D_ * D_ / 4 + 255) / 256, 4), 256>>>(
        wq, wk, wv, wo, wqb, wkb, wvb, wob);

    lin_qkv<<<dim3(D_ / 128, MROWS / 128, 3), 256, LSMEM>>>(
        srcb, wqb, wkb, wvb, bq, bk, bv, qb, kb, vb);

    flash_k<<<dim3(S_ / 128, B_ * H_), 256, FSMEM>>>(qb, kb, vb, ctxb);

    lin_o<<<dim3(D_ / 128, MROWS / 128), 256, LSMEM>>>(ctxb, wob, bo, tmp);

    add_ln_k<1, true><<<MROWS, 128>>>(src, tmp, nullptr, g1, b1, x, xf);

    // conv1: M-tiles of 256 (grid.y = 32)
    conv_tap<D_, F_, D_ / 64, true><<<dim3(F_ / 128, MROWS / 256, 1), 256, CSMEM>>>(
        xf, w1f, c1b, h1f, nullptr);
    // conv2: split-K 2
    conv_tap<F_, D_, F_ / 128, false><<<dim3(D_ / 128, MROWS / 256, 2), 256, CSMEM>>>(
        h1f, w2f, c2b, nullptr, ffn);

    add_ln_k<2, false><<<MROWS, 128>>>(x, ffn, ffn + (long)MROWS * D_, g2, b2, out, nullptr);
}

// round 12
// speedup vs baseline: 1.0139x; 1.0139x over previous
#include <cuda_runtime.h>
#include <cuda_bf16.h>
#include <cuda_fp16.h>
#include <cstdint>

#define B_ 4
#define S_ 2048
#define D_ 512
#define H_ 8
#define DK_ 64
#define F_ 2048
#define K_ 9
#define PAD_ 4
#define EPSLN 1e-5f

static const int MROWS = B_ * S_;  // 8192

// ---------------- scratch ----------------
__device__ float g_tmp[B_ * S_ * D_];
__device__ float g_x[B_ * S_ * D_];
__device__ float g_ffn[2 * B_ * S_ * D_];
__device__ __half g_srch[B_ * S_ * D_];
__device__ __half g_wqh[D_ * D_];
__device__ __half g_wkh[D_ * D_];
__device__ __half g_wvh[D_ * D_];
__device__ __half g_woh[D_ * D_];
__device__ __half g_qh[B_ * S_ * D_];
__device__ __half g_kh[B_ * S_ * D_];
__device__ __half g_vh[B_ * S_ * D_];
__device__ __half g_ctxh[B_ * S_ * D_];
__device__ __half g_xf[B_ * S_ * D_];
__device__ __half g_h1f[B_ * S_ * F_];
__device__ __half g_w1f[F_ * K_ * D_];
__device__ __half g_w2f[D_ * K_ * F_];

// ================= helpers =================
__device__ __forceinline__ uint32_t smem_u32(const void* p) {
    uint32_t a;
    asm("{ .reg .u64 t; cvta.to.shared.u64 t, %1; cvt.u32.u64 %0, t; }" : "=r"(a) : "l"(p));
    return a;
}
__device__ __forceinline__ void cp16(uint32_t dst, const void* src, uint32_t sz) {
    asm volatile("cp.async.cg.shared.global [%0], [%1], 16, %2;"
                 :: "r"(dst), "l"(src), "r"(sz) : "memory");
}
__device__ __forceinline__ void mma_f16(float* d, const uint32_t* a, const uint32_t* b) {
    asm volatile(
        "mma.sync.aligned.m16n8k16.row.col.f32.f16.f16.f32 "
        "{%0,%1,%2,%3}, {%4,%5,%6,%7}, {%8,%9}, {%0,%1,%2,%3};"
        : "+f"(d[0]), "+f"(d[1]), "+f"(d[2]), "+f"(d[3])
        : "r"(a[0]), "r"(a[1]), "r"(a[2]), "r"(a[3]), "r"(b[0]), "r"(b[1]));
}
// pack two fp32 into fp16x2: lo = x, hi = y
__device__ __forceinline__ uint32_t packh(float x, float y) {
    uint32_t r;
    asm("cvt.rn.f16x2.f32 %0, %1, %2;" : "=r"(r) : "f"(y), "f"(x));
    return r;
}
__device__ __forceinline__ uint32_t ex2h2(uint32_t a) {
    uint32_t r;
    asm("ex2.approx.f16x2 %0, %1;" : "=r"(r) : "r"(a));
    return r;
}

// ============== conv, M-tile 128, tap reuse (round-10 proven config) =========
template <int CIN, int NF, int NDBLK, bool RELU>
__global__ void __launch_bounds__(256, 2)
conv_tap(const __half* __restrict__ Af, const __half* __restrict__ Bf,
         const float* __restrict__ bias,
         __half* __restrict__ ofh, float* __restrict__ off) {
    constexpr int KTOT = K_ * CIN;
    constexpr int RSTR = 144;
    constexpr int ATILE = 136 * RSTR;
    constexpr int BTILE = 128 * RSTR;
    constexpr int NIT = NDBLK * 9;

    extern __shared__ __align__(16) char sm[];
    const int tid = threadIdx.x;
    const int lane = tid & 31;
    const int w = tid >> 5;
    const int wm = w & 3;
    const int wn = w >> 2;
    const int m0 = blockIdx.y * 128;
    const int n0 = blockIdx.x * 128;
    const int dz0 = blockIdx.z * NDBLK;
    const int bbase = m0 & ~(S_ - 1);
    const int s0 = m0 & (S_ - 1);

    float acc[2][8][4];
#pragma unroll
    for (int i = 0; i < 2; i++)
#pragma unroll
        for (int j = 0; j < 8; j++)
#pragma unroll
            for (int e = 0; e < 4; e++) acc[i][j][e] = 0.f;

    const uint32_t smu = smem_u32(sm);
    const uint32_t A0u = smu, A1u = smu + ATILE;
    const uint32_t B0u = smu + 2 * ATILE, B1u = smu + 2 * ATILE + BTILE;

    auto loadA = [&](int dblk, int buf) {
        uint32_t base = buf ? A1u : A0u;
        int dcol = (dz0 + dblk) << 6;
        for (int t = tid; t < 1088; t += 256) {
            int r = t >> 3, u = t & 7;
            int srow = s0 + r - PAD_;
            bool val = (unsigned)srow < (unsigned)S_;
            long aoff = (long)(bbase + (val ? srow : 0)) * CIN + dcol + (u << 3);
            cp16(base + r * RSTR + (u << 4), Af + aoff, val ? 16u : 0u);
        }
    };
    auto loadB = [&](int dblk, int k, int buf) {
        uint32_t base = buf ? B1u : B0u;
        long kk0 = (long)k * CIN + ((dz0 + dblk) << 6);
#pragma unroll
        for (int j = 0; j < 4; j++) {
            int idx = tid + j * 256;
            int r = idx >> 3, u = idx & 7;
            cp16(base + r * RSTR + (u << 4), Bf + (long)(n0 + r) * KTOT + kk0 + (u << 3), 16);
        }
    };

    loadA(0, 0);
    loadB(0, 0, 0);
    asm volatile("cp.async.commit_group;" ::: "memory");

    const int arow = lane >> 2;
    const int acol = (lane & 3) * 4;
    int abuf = 0;

    for (int i = 0; i < NIT; i++) {
        const int dblk = i / 9;
        const int k = i - dblk * 9;
        if (i + 1 < NIT) {
            const int k1 = (k == 8) ? 0 : k + 1;
            const int d1 = (k == 8) ? dblk + 1 : dblk;
            loadB(d1, k1, (i + 1) & 1);
            if (k == 8) loadA(d1, abuf ^ 1);
        }
        asm volatile("cp.async.commit_group;" ::: "memory");
        asm volatile("cp.async.wait_group 1;" ::: "memory");
        __syncthreads();

        const char* A_s = sm + (abuf ? ATILE : 0);
        const char* B_s = sm + 2 * ATILE + ((i & 1) ? BTILE : 0);

#pragma unroll
        for (int ks = 0; ks < 4; ks++) {
            const int kb = ks * 32;
            uint32_t ar[2][4], br[8][2];
#pragma unroll
            for (int mi = 0; mi < 2; mi++) {
                const char* ba = A_s + (wm * 32 + mi * 16 + arow + k) * RSTR + kb + acol;
                ar[mi][0] = *(const uint32_t*)ba;
                ar[mi][1] = *(const uint32_t*)(ba + 8 * RSTR);
                ar[mi][2] = *(const uint32_t*)(ba + 16);
                ar[mi][3] = *(const uint32_t*)(ba + 8 * RSTR + 16);
            }
#pragma unroll
            for (int nj = 0; nj < 8; nj++) {
                const char* bb = B_s + (wn * 64 + nj * 8 + arow) * RSTR + kb + acol;
                br[nj][0] = *(const uint32_t*)bb;
                br[nj][1] = *(const uint32_t*)(bb + 16);
            }
#pragma unroll
            for (int mi = 0; mi < 2; mi++)
#pragma unroll
                for (int nj = 0; nj < 8; nj++) mma_f16(acc[mi][nj], ar[mi], br[nj]);
        }
        __syncthreads();
        if (k == 8) abuf ^= 1;
    }

    const int mbase = m0 + wm * 32;
    const int nb0 = n0 + wn * 64;
    const long zoff = (long)blockIdx.z * MROWS * D_;
#pragma unroll
    for (int mi = 0; mi < 2; mi++) {
        const int m = mbase + mi * 16 + arow;
#pragma unroll
        for (int nj = 0; nj < 8; nj++) {
            const int n = nb0 + nj * 8 + (lane & 3) * 2;
            if (RELU) {
                const float bv0 = bias[n], bv1 = bias[n + 1];
                __half2 p0, p1;
                p0.x = __float2half_rn(fmaxf(acc[mi][nj][0] + bv0, 0.f));
                p0.y = __float2half_rn(fmaxf(acc[mi][nj][1] + bv1, 0.f));
                p1.x = __float2half_rn(fmaxf(acc[mi][nj][2] + bv0, 0.f));
                p1.y = __float2half_rn(fmaxf(acc[mi][nj][3] + bv1, 0.f));
                *(__half2*)(ofh + (long)m * NF + n) = p0;
                *(__half2*)(ofh + (long)(m + 8) * NF + n) = p1;
            } else {
                const float bv0 = blockIdx.z == 0 ? bias[n] : 0.f;
                const float bv1 = blockIdx.z == 0 ? bias[n + 1] : 0.f;
                *(float2*)(off + zoff + (long)m * NF + n) =
                    make_float2(acc[mi][nj][0] + bv0, acc[mi][nj][1] + bv1);
                *(float2*)(off + zoff + (long)(m + 8) * NF + n) =
                    make_float2(acc[mi][nj][2] + bv0, acc[mi][nj][3] + bv1);
            }
        }
    }
}

// ============== fp16 linear (QKV projections), z selects weight ==============
__global__ void __launch_bounds__(256, 2)
lin_qkv(const __half* __restrict__ A,
        const __half* __restrict__ W0, const __half* __restrict__ W1,
        const __half* __restrict__ W2,
        const float* __restrict__ bi0, const float* __restrict__ bi1,
        const float* __restrict__ bi2,
        __half* __restrict__ o0, __half* __restrict__ o1, __half* __restrict__ o2) {
    constexpr int RSTR = 144;
    constexpr int TILE = 128 * RSTR;
    constexpr int BUF = 2 * TILE;

    extern __shared__ __align__(16) char sm[];
    const int z = blockIdx.z;
    const __half* W = (z == 0) ? W0 : (z == 1) ? W1 : W2;
    const float* bias = (z == 0) ? bi0 : (z == 1) ? bi1 : bi2;
    __half* out = (z == 0) ? o0 : (z == 1) ? o1 : o2;

    const int tid = threadIdx.x;
    const int lane = tid & 31;
    const int w = tid >> 5;
    const int wm = w & 3;
    const int wn = w >> 2;
    const int m0 = blockIdx.y * 128;
    const int n0 = blockIdx.x * 128;

    float acc[2][8][4];
#pragma unroll
    for (int i = 0; i < 2; i++)
#pragma unroll
        for (int j = 0; j < 8; j++)
#pragma unroll
            for (int e = 0; e < 4; e++) acc[i][j][e] = 0.f;

    const uint32_t smu = smem_u32(sm);
    auto prefetch = [&](int c) {
        uint32_t bpu = smu + (c & 1) * BUF;
#pragma unroll
        for (int j = 0; j < 4; j++) {
            int idx = tid + j * 256;
            int r = idx >> 3, u = idx & 7;
            uint32_t d = bpu + r * RSTR + (u << 4);
            cp16(d, A + (long)(m0 + r) * D_ + c * 64 + (u << 3), 16);
            cp16(d + TILE, W + (long)(n0 + r) * D_ + c * 64 + (u << 3), 16);
        }
    };

    prefetch(0);
    asm volatile("cp.async.commit_group;" ::: "memory");
    const int arow = lane >> 2;
    const int acol = (lane & 3) * 4;

    for (int c = 0; c < D_ / 64; ++c) {
        if (c + 1 < D_ / 64) {
            prefetch(c + 1);
            asm volatile("cp.async.commit_group;" ::: "memory");
            asm volatile("cp.async.wait_group 1;" ::: "memory");
        } else {
            asm volatile("cp.async.wait_group 0;" ::: "memory");
        }
        __syncthreads();
        const char* bp = sm + (c & 1) * BUF;
#pragma unroll
        for (int ks = 0; ks < 4; ks++) {
            const int kb = ks * 32;
            uint32_t ar[2][4], br[8][2];
#pragma unroll
            for (int mi = 0; mi < 2; mi++) {
                const char* ba = bp + (wm * 32 + mi * 16 + arow) * RSTR + kb + acol;
                ar[mi][0] = *(const uint32_t*)ba;
                ar[mi][1] = *(const uint32_t*)(ba + 8 * RSTR);
                ar[mi][2] = *(const uint32_t*)(ba + 16);
                ar[mi][3] = *(const uint32_t*)(ba + 8 * RSTR + 16);
            }
#pragma unroll
            for (int nj = 0; nj < 8; nj++) {
                const char* bb = bp + TILE + (wn * 64 + nj * 8 + arow) * RSTR + kb + acol;
                br[nj][0] = *(const uint32_t*)bb;
                br[nj][1] = *(const uint32_t*)(bb + 16);
            }
#pragma unroll
            for (int mi = 0; mi < 2; mi++)
#pragma unroll
                for (int nj = 0; nj < 8; nj++) mma_f16(acc[mi][nj], ar[mi], br[nj]);
        }
        __syncthreads();
    }

    const int mbase = m0 + wm * 32;
    const int nb0 = n0 + wn * 64;
#pragma unroll
    for (int mi = 0; mi < 2; mi++) {
        const int m = mbase + mi * 16 + arow;
#pragma unroll
        for (int nj = 0; nj < 8; nj++) {
            const int n = nb0 + nj * 8 + (lane & 3) * 2;
            const float bv0 = bias[n], bv1 = bias[n + 1];
            uint32_t p0 = packh(acc[mi][nj][0] + bv0, acc[mi][nj][1] + bv1);
            uint32_t p1 = packh(acc[mi][nj][2] + bv0, acc[mi][nj][3] + bv1);
            *(uint32_t*)(out + (long)m * D_ + n) = p0;
            *(uint32_t*)(out + (long)(m + 8) * D_ + n) = p1;
        }
    }
}

// ============== fp16 linear, fp32 output (wo projection) =====================
__global__ void __launch_bounds__(256, 2)
lin_o(const __half* __restrict__ A, const __half* __restrict__ W,
      const float* __restrict__ bias, float* __restrict__ out) {
    constexpr int RSTR = 144;
    constexpr int TILE = 128 * RSTR;
    constexpr int BUF = 2 * TILE;

    extern __shared__ __align__(16) char sm[];
    const int tid = threadIdx.x;
    const int lane = tid & 31;
    const int w = tid >> 5;
    const int wm = w & 3;
    const int wn = w >> 2;
    const int m0 = blockIdx.y * 128;
    const int n0 = blockIdx.x * 128;

    float acc[2][8][4];
#pragma unroll
    for (int i = 0; i < 2; i++)
#pragma unroll
        for (int j = 0; j < 8; j++)
#pragma unroll
            for (int e = 0; e < 4; e++) acc[i][j][e] = 0.f;

    const uint32_t smu = smem_u32(sm);
    auto prefetch = [&](int c) {
        uint32_t bpu = smu + (c & 1) * BUF;
#pragma unroll
        for (int j = 0; j < 4; j++) {
            int idx = tid + j * 256;
            int r = idx >> 3, u = idx & 7;
            uint32_t d = bpu + r * RSTR + (u << 4);
            cp16(d, A + (long)(m0 + r) * D_ + c * 64 + (u << 3), 16);
            cp16(d + TILE, W + (long)(n0 + r) * D_ + c * 64 + (u << 3), 16);
        }
    };

    prefetch(0);
    asm volatile("cp.async.commit_group;" ::: "memory");
    const int arow = lane >> 2;
    const int acol = (lane & 3) * 4;

    for (int c = 0; c < D_ / 64; ++c) {
        if (c + 1 < D_ / 64) {
            prefetch(c + 1);
            asm volatile("cp.async.commit_group;" ::: "memory");
            asm volatile("cp.async.wait_group 1;" ::: "memory");
        } else {
            asm volatile("cp.async.wait_group 0;" ::: "memory");
        }
        __syncthreads();
        const char* bp = sm + (c & 1) * BUF;
#pragma unroll
        for (int ks = 0; ks < 4; ks++) {
            const int kb = ks * 32;
            uint32_t ar[2][4], br[8][2];
#pragma unroll
            for (int mi = 0; mi < 2; mi++) {
                const char* ba = bp + (wm * 32 + mi * 16 + arow) * RSTR + kb + acol;
                ar[mi][0] = *(const uint32_t*)ba;
                ar[mi][1] = *(const uint32_t*)(ba + 8 * RSTR);
                ar[mi][2] = *(const uint32_t*)(ba + 16);
                ar[mi][3] = *(const uint32_t*)(ba + 8 * RSTR + 16);
            }
#pragma unroll
            for (int nj = 0; nj < 8; nj++) {
                const char* bb = bp + TILE + (wn * 64 + nj * 8 + arow) * RSTR + kb + acol;
                br[nj][0] = *(const uint32_t*)bb;
                br[nj][1] = *(const uint32_t*)(bb + 16);
            }
#pragma unroll
            for (int mi = 0; mi < 2; mi++)
#pragma unroll
                for (int nj = 0; nj < 8; nj++) mma_f16(acc[mi][nj], ar[mi], br[nj]);
        }
        __syncthreads();
    }

    const int mbase = m0 + wm * 32;
    const int nb0 = n0 + wn * 64;
#pragma unroll
    for (int mi = 0; mi < 2; mi++) {
        const int m = mbase + mi * 16 + arow;
#pragma unroll
        for (int nj = 0; nj < 8; nj++) {
            const int n = nb0 + nj * 8 + (lane & 3) * 2;
            const float bv0 = bias[n], bv1 = bias[n + 1];
            *(float2*)(out + (long)m * D_ + n) =
                make_float2(acc[mi][nj][0] + bv0, acc[mi][nj][1] + bv1);
            *(float2*)(out + (long)(m + 8) * D_ + n) =
                make_float2(acc[mi][nj][2] + bv0, acc[mi][nj][3] + bv1);
        }
    }
}

// ====== fused flash attention: fp16, ex2.approx.f16x2 softmax ================
__global__ void __launch_bounds__(256, 2)
flash_k(const __half* __restrict__ qg, const __half* __restrict__ kg,
        const __half* __restrict__ vg, __half* __restrict__ ctx) {
    constexpr int QPITCH = 144;
    constexpr int KPITCH = 144;
    constexpr int VPITCH = 276;
    extern __shared__ __align__(16) char sm[];
    char* Qs = sm;
    char* Ks = sm + 128 * QPITCH;
    char* Vt = Ks + 128 * KPITCH;

    const int tid = threadIdx.x;
    const int lane = tid & 31;
    const int w = tid >> 5;
    const int bh = blockIdx.y;
    const int b = bh >> 3, h = bh & 7;
    const int q0 = blockIdx.x * 128;
    const long hoff = (long)b * S_ * D_ + h * DK_;
    const __half* qp = qg + hoff;
    const __half* kp = kg + hoff;
    const __half* vp = vg + hoff;

    const uint32_t qsu = smem_u32(Qs);
    const uint32_t ksu = smem_u32(Ks);

#pragma unroll
    for (int i = 0; i < 4; i++) {
        int idx = tid + i * 256;
        int r = idx >> 3, u = idx & 7;
        cp16(qsu + r * QPITCH + (u << 4), qp + (long)(q0 + r) * D_ + (u << 3), 16);
    }
    asm volatile("cp.async.commit_group;" ::: "memory");
    asm volatile("cp.async.wait_group 0;" ::: "memory");
    __syncthreads();

    const int arow = lane >> 2;
    const int acol = (lane & 3) * 4;
    uint32_t qf[4][4];
#pragma unroll
    for (int ks = 0; ks < 4; ks++) {
        const char* ba = Qs + (w * 16 + arow) * QPITCH + ks * 32 + acol;
        qf[ks][0] = *(const uint32_t*)ba;
        qf[ks][1] = *(const uint32_t*)(ba + 8 * QPITCH);
        qf[ks][2] = *(const uint32_t*)(ba + 16);
        qf[ks][3] = *(const uint32_t*)(ba + 8 * QPITCH + 16);
    }

    float oacc[8][4];
#pragma unroll
    for (int j = 0; j < 8; j++)
#pragma unroll
        for (int e = 0; e < 4; e++) oacc[j][e] = 0.f;
    float lsum0 = 0.f, lsum1 = 0.f;
    const float CSC = 0.125f * 1.4426950408889634f;  // log2(e)/8

    for (int t = 0; t < S_ / 128; ++t) {
        __syncthreads();
#pragma unroll
        for (int i = 0; i < 4; i++) {
            int idx = tid + i * 256;
            int r = idx >> 3, u = idx & 7;
            cp16(ksu + r * KPITCH + (u << 4), kp + (long)(t * 128 + r) * D_ + (u << 3), 16);
        }
        asm volatile("cp.async.commit_group;" ::: "memory");
#pragma unroll
        for (int i = 0; i < 2; i++) {
            int idx = tid + i * 256;
            int k2 = idx >> 3, u = idx & 7;
            const uint4 a = *(const uint4*)(vp + (long)(t * 128 + 2 * k2) * D_ + (u << 3));
            const uint4 bq = *(const uint4*)(vp + (long)(t * 128 + 2 * k2 + 1) * D_ + (u << 3));
            const uint32_t va[4] = {a.x, a.y, a.z, a.w};
            const uint32_t vb[4] = {bq.x, bq.y, bq.z, bq.w};
#pragma unroll
            for (int e = 0; e < 8; e++) {
                uint32_t lo = (va[e >> 1] >> ((e & 1) * 16)) & 0xffffu;
                uint32_t hi = (vb[e >> 1] >> ((e & 1) * 16)) & 0xffffu;
                *(uint32_t*)(Vt + (u * 8 + e) * VPITCH + k2 * 4) = lo | (hi << 16);
            }
        }
        asm volatile("cp.async.wait_group 0;" ::: "memory");
        __syncthreads();

        float sacc[16][4];
#pragma unroll
        for (int j = 0; j < 16; j++)
#pragma unroll
            for (int e = 0; e < 4; e++) sacc[j][e] = 0.f;
#pragma unroll
        for (int ks = 0; ks < 4; ks++) {
#pragma unroll
            for (int nt = 0; nt < 16; nt++) {
                const char* bb = Ks + (nt * 8 + arow) * KPITCH + ks * 32 + acol;
                uint32_t br[2];
                br[0] = *(const uint32_t*)bb;
                br[1] = *(const uint32_t*)(bb + 16);
                mma_f16(sacc[nt], qf[ks], br);
            }
        }
        // P = 2^(s*log2e/8) via ex2.approx.f16x2 — output is the packed fp16
        // P fragment directly; lsum accumulated in fp32.
        uint32_t ph[16][2];
#pragma unroll
        for (int nt = 0; nt < 16; nt++) {
            uint32_t h01 = packh(sacc[nt][0] * CSC, sacc[nt][1] * CSC);
            uint32_t h23 = packh(sacc[nt][2] * CSC, sacc[nt][3] * CSC);
            h01 = ex2h2(h01);
            h23 = ex2h2(h23);
            ph[nt][0] = h01;
            ph[nt][1] = h23;
            float2 f01 = __half22float2(*(__half2*)&h01);
            float2 f23 = __half22float2(*(__half2*)&h23);
            lsum0 += f01.x + f01.y;
            lsum1 += f23.x + f23.y;
        }
#pragma unroll
        for (int kt = 0; kt < 8; kt++) {
            uint32_t pa[4];
            pa[0] = ph[2 * kt][0];
            pa[1] = ph[2 * kt][1];
            pa[2] = ph[2 * kt + 1][0];
            pa[3] = ph[2 * kt + 1][1];
#pragma unroll
            for (int nt = 0; nt < 8; nt++) {
                const char* bb = Vt + (nt * 8 + arow) * VPITCH + kt * 32 + acol;
                uint32_t br[2];
                br[0] = *(const uint32_t*)bb;
                br[1] = *(const uint32_t*)(bb + 16);
                mma_f16(oacc[nt], pa, br);
            }
        }
    }

    lsum0 += __shfl_xor_sync(0xffffffffu, lsum0, 1);
    lsum0 += __shfl_xor_sync(0xffffffffu, lsum0, 2);
    lsum1 += __shfl_xor_sync(0xffffffffu, lsum1, 1);
    lsum1 += __shfl_xor_sync(0xffffffffu, lsum1, 2);
    const float inv0 = 1.f / lsum0;
    const float inv1 = 1.f / lsum1;

    const int row0 = q0 + w * 16 + arow;
#pragma unroll
    for (int nt = 0; nt < 8; nt++) {
        const int col = h * DK_ + nt * 8 + (lane & 3) * 2;
        *(uint32_t*)(ctx + ((long)b * S_ + row0) * D_ + col) =
            packh(oacc[nt][0] * inv0, oacc[nt][1] * inv0);
        *(uint32_t*)(ctx + ((long)b * S_ + row0 + 8) * D_ + col) =
            packh(oacc[nt][2] * inv1, oacc[nt][3] * inv1);
    }
}

// ---------------- converts & weight reorders (coalesced) ---------------------
__global__ void f2h(const float* __restrict__ in, __half* __restrict__ out, int n) {
    int i = (blockIdx.x * 256 + threadIdx.x) * 4;
    if (i >= n) return;
    float4 v = *(const float4*)(in + i);
    __half o[4] = {__float2half_rn(v.x), __float2half_rn(v.y),
                   __float2half_rn(v.z), __float2half_rn(v.w)};
    *(uint2*)(out + i) = *(uint2*)o;
}
__global__ void f2h_w4(const float* __restrict__ w0, const float* __restrict__ w1,
                       const float* __restrict__ w2, const float* __restrict__ w3,
                       __half* __restrict__ o0, __half* __restrict__ o1,
                       __half* __restrict__ o2, __half* __restrict__ o3) {
    const int z = blockIdx.y;
    const float* in = (z == 0) ? w0 : (z == 1) ? w1 : (z == 2) ? w2 : w3;
    __half* out = (z == 0) ? o0 : (z == 1) ? o1 : (z == 2) ? o2 : o3;
    int i = (blockIdx.x * 256 + threadIdx.x) * 4;
    if (i >= D_ * D_) return;
    float4 v = *(const float4*)(in + i);
    __half o[4] = {__float2half_rn(v.x), __float2half_rn(v.y),
                   __float2half_rn(v.z), __float2half_rn(v.w)};
    *(uint2*)(out + i) = *(uint2*)o;
}
__global__ void cvt_w1_t(const float* __restrict__ w, __half* __restrict__ o) {
    __shared__ float s[D_ * K_];
    const int f = blockIdx.x;
    const float* src = w + (long)f * (D_ * K_);
    for (int j = threadIdx.x; j < D_ * K_; j += 256) s[j] = src[j];
    __syncthreads();
    __half* dst = o + (long)f * (K_ * D_);
    for (int t = threadIdx.x; t < K_ * D_; t += 256) {
        int k = t / D_, d = t - k * D_;
        dst[t] = __float2half_rn(s[d * K_ + k]);
    }
}
__global__ void cvt_w2_t(const float* __restrict__ w, __half* __restrict__ o) {
    __shared__ __half s[F_ * K_];
    const int d = blockIdx.x;
    const float* src = w + (long)d * (F_ * K_);
    for (int j = threadIdx.x; j < F_ * K_; j += 256) s[j] = __float2half_rn(src[j]);
    __syncthreads();
    __half* dst = o + (long)d * (K_ * F_);
    for (int t = threadIdx.x; t < K_ * F_; t += 256) {
        int k = t / F_, fi = t - k * F_;
        dst[t] = s[fi * K_ + k];
    }
}

// ------------- residual add + LayerNorm (1 or 2 residual-add inputs) --------
template <int NB, bool EMIT16>
__global__ void add_ln_k(const float* __restrict__ a, const float* __restrict__ b0,
                         const float* __restrict__ b1,
                         const float* __restrict__ g, const float* __restrict__ be,
                         float* __restrict__ o, __half* __restrict__ o16) {
    __shared__ float sh[8];
    long row = blockIdx.x;
    int t = threadIdx.x;
    int lane = t & 31, wid = t >> 5;
    float4 va = ((const float4*)(a + row * D_))[t];
    float4 vb = ((const float4*)(b0 + row * D_))[t];
    float4 v;
    v.x = va.x + vb.x; v.y = va.y + vb.y; v.z = va.z + vb.z; v.w = va.w + vb.w;
    if (NB == 2) {
        float4 vc = ((const float4*)(b1 + row * D_))[t];
        v.x += vc.x; v.y += vc.y; v.z += vc.z; v.w += vc.w;
    }
    float s = v.x + v.y + v.z + v.w;
    float s2 = v.x * v.x + v.y * v.y + v.z * v.z + v.w * v.w;
#pragma unroll
    for (int off = 16; off; off >>= 1) {
        s += __shfl_xor_sync(0xffffffffu, s, off);
        s2 += __shfl_xor_sync(0xffffffffu, s2, off);
    }
    if (lane == 0) { sh[wid] = s; sh[4 + wid] = s2; }
    __syncthreads();
    float S = sh[0] + sh[1] + sh[2] + sh[3];
    float S2 = sh[4] + sh[5] + sh[6] + sh[7];
    float mean = S * (1.f / D_);
    float var = S2 * (1.f / D_) - mean * mean;
    float inv = rsqrtf(var + EPSLN);
    float4 g4 = ((const float4*)g)[t];
    float4 b4 = ((const float4*)be)[t];
    float4 r;
    r.x = (v.x - mean) * inv * g4.x + b4.x;
    r.y = (v.y - mean) * inv * g4.y + b4.y;
    r.z = (v.z - mean) * inv * g4.z + b4.z;
    r.w = (v.w - mean) * inv * g4.w + b4.w;
    ((float4*)(o + row * D_))[t] = r;
    if (EMIT16) {
        __half hs[4] = {__float2half_rn(r.x), __float2half_rn(r.y),
                        __float2half_rn(r.z), __float2half_rn(r.w)};
        *(uint2*)(o16 + row * D_ + t * 4) = *(uint2*)hs;
    }
}

// ---------------- launch ------------------------------------------------------
extern "C" void kernel_launch(void* const* d_in, const int* in_sizes, int n_in,
                              void* d_out, int out_size) {
    const float* src = (const float*)d_in[0];
    const float* wq = (const float*)d_in[2];
    const float* bq = (const float*)d_in[3];
    const float* wk = (const float*)d_in[4];
    const float* bk = (const float*)d_in[5];
    const float* wv = (const float*)d_in[6];
    const float* bv = (const float*)d_in[7];
    const float* wo = (const float*)d_in[8];
    const float* bo = (const float*)d_in[9];
    const float* c1w = (const float*)d_in[10];
    const float* c1b = (const float*)d_in[11];
    const float* c2w = (const float*)d_in[12];
    const float* c2b = (const float*)d_in[13];
    const float* g1 = (const float*)d_in[14];
    const float* b1 = (const float*)d_in[15];
    const float* g2 = (const float*)d_in[16];
    const float* b2 = (const float*)d_in[17];
    float* out = (float*)d_out;

    float *tmp, *x, *ffn;
    __half *srch, *wqh, *wkh, *wvh, *woh, *qh, *kh, *vh, *ctxh;
    __half *xf, *h1f, *w1f, *w2f;
    cudaGetSymbolAddress((void**)&tmp, g_tmp);
    cudaGetSymbolAddress((void**)&x, g_x);
    cudaGetSymbolAddress((void**)&ffn, g_ffn);
    cudaGetSymbolAddress((void**)&srch, g_srch);
    cudaGetSymbolAddress((void**)&wqh, g_wqh);
    cudaGetSymbolAddress((void**)&wkh, g_wkh);
    cudaGetSymbolAddress((void**)&wvh, g_wvh);
    cudaGetSymbolAddress((void**)&woh, g_woh);
    cudaGetSymbolAddress((void**)&qh, g_qh);
    cudaGetSymbolAddress((void**)&kh, g_kh);
    cudaGetSymbolAddress((void**)&vh, g_vh);
    cudaGetSymbolAddress((void**)&ctxh, g_ctxh);
    cudaGetSymbolAddress((void**)&xf, g_xf);
    cudaGetSymbolAddress((void**)&h1f, g_h1f);
    cudaGetSymbolAddress((void**)&w1f, g_w1f);
    cudaGetSymbolAddress((void**)&w2f, g_w2f);

    const int CSMEM = 2 * 136 * 144 + 2 * 128 * 144;    // 76032
    const int LSMEM = 2 * 2 * 128 * 144;                 // 73728
    const int FSMEM = 128 * 144 + 128 * 144 + 64 * 276;  // 54528
    cudaFuncSetAttribute(conv_tap<D_, F_, D_ / 64, true>,
                         cudaFuncAttributeMaxDynamicSharedMemorySize, CSMEM);
    cudaFuncSetAttribute(conv_tap<F_, D_, F_ / 128, false>,
                         cudaFuncAttributeMaxDynamicSharedMemorySize, CSMEM);
    cudaFuncSetAttribute(lin_qkv, cudaFuncAttributeMaxDynamicSharedMemorySize, LSMEM);
    cudaFuncSetAttribute(lin_o, cudaFuncAttributeMaxDynamicSharedMemorySize, LSMEM);
    cudaFuncSetAttribute(flash_k, cudaFuncAttributeMaxDynamicSharedMemorySize, FSMEM);

    cvt_w1_t<<<F_, 256>>>(c1w, w1f);
    cvt_w2_t<<<D_, 256>>>(c2w, w2f);
    f2h<<<(MROWS * D_ / 4 + 255) / 256, 256>>>(src, srch, MROWS * D_);
    f2h_w4<<<dim3((D_ * D_ / 4 + 255) / 256, 4), 256>>>(
        wq, wk, wv, wo, wqh, wkh, wvh, woh);

    lin_qkv<<<dim3(D_ / 128, MROWS / 128, 3), 256, LSMEM>>>(
        srch, wqh, wkh, wvh, bq, bk, bv, qh, kh, vh);

    flash_k<<<dim3(S_ / 128, B_ * H_), 256, FSMEM>>>(qh, kh, vh, ctxh);

    lin_o<<<dim3(D_ / 128, MROWS / 128), 256, LSMEM>>>(ctxh, woh, bo, tmp);

    add_ln_k<1, true><<<MROWS, 128>>>(src, tmp, nullptr, g1, b1, x, xf);

    conv_tap<D_, F_, D_ / 64, true><<<dim3(F_ / 128, MROWS / 128, 1), 256, CSMEM>>>(
        xf, w1f, c1b, h1f, nullptr);
    conv_tap<F_, D_, F_ / 128, false><<<dim3(D_ / 128, MROWS / 128, 2), 256, CSMEM>>>(
        h1f, w2f, c2b, nullptr, ffn);

    add_ln_k<2, false><<<MROWS, 128>>>(x, ffn, ffn + (long)MROWS * D_, g2, b2, out, nullptr);
}